// round 8
// baseline (speedup 1.0000x reference)
#include <cuda_runtime.h>

#define ALPHA 0.2f
#define MASKV -9000000000000000.0f
using ull  = unsigned long long;
using ull2 = ulonglong2;

__constant__ __align__(16) float cW1[96];     // (3,1,32)
__constant__ __align__(16) float cA1[192];    // (3,64,1)
__constant__ __align__(16) float cW2[4608];   // (3,96,16)
__constant__ __align__(16) float cA2[96];     // (3,32,1)
__constant__ __align__(16) float cWp1[1152];  // (48,24)
__constant__ __align__(16) float cBp1[24];
__constant__ __align__(16) float cWp2[24];
__constant__ __align__(16) float cBp2[4];
__constant__ __align__(16) float cAdj[84];

#define NTHR 128
#define MAXBLK 1024
#define NT (MAXBLK*NTHR)

__device__ float    g_c12[6];                // c1[3], c2[3]
__device__ unsigned g_mrow[9];               // adjacency bitmask per row
__device__ ull      g_wh[(size_t)72  * NT];  // per-head Wh tile (9 rows x 8 pairs)
__device__ ull      g_h2[(size_t)216 * NT];  // h2 pairs (9 rows x 24 pairs)

__device__ __forceinline__ void ffma2(ull& d, ull a, ull b) {
    asm("fma.rn.f32x2 %0, %1, %2, %0;" : "+l"(d) : "l"(a), "l"(b));
}
__device__ __forceinline__ ull dup2(float x) {
    ull r; asm("mov.b64 %0, {%1, %1};" : "=l"(r) : "f"(x)); return r;
}
__device__ __forceinline__ float2 unp(ull v) {
    float2 r; asm("mov.b64 {%0, %1}, %2;" : "=f"(r.x), "=f"(r.y) : "l"(v)); return r;
}
__device__ __forceinline__ float tanh_fast(float x) {
    float r; asm("tanh.approx.f32 %0, %1;" : "=f"(r) : "f"(x)); return r;
}
__device__ __forceinline__ ull c64(const float* p) {
    return __double_as_longlong(*(const double*)(const void*)p);
}
__device__ __forceinline__ float lrelu(float x) { return fmaxf(x, ALPHA * x); }
__device__ __forceinline__ float elu(float x) {
    return (x > 0.f) ? x : (__expf(x) - 1.f);
}

__global__ void prep_kernel() {
    int t = threadIdx.x;
    if (t < 6) {
        int h = t % 3, half = t / 3;
        float s = 0.f;
        #pragma unroll
        for (int d = 0; d < 32; d++)
            s += cW1[h*32 + d] * cA1[h*64 + half*32 + d];
        g_c12[half*3 + h] = s;
    }
    if (t < 9) {
        unsigned m = 0;
        for (int j = 0; j < 9; j++)
            if (cAdj[t*9 + j] > 0.f) m |= (1u << j);
        g_mrow[t] = m;
    }
}

__global__ void __launch_bounds__(NTHR, 4)
gnn_main(const float* __restrict__ g_obs, float* __restrict__ g_out, int B)
{
    __shared__ float sS[NTHR * 29];   // per-thread s1[27] (stride 29, odd)
    __shared__ ull2  sW2s[1152];      // W2 pairs (raw layout of cW2)
    __shared__ ull2  sWp1[288];       // Wp1 pairs (raw layout of cWp1)

    const int tid  = threadIdx.x;
    const int gtid = blockIdx.x * NTHR + tid;
    const int stride = gridDim.x * NTHR;
    float* sTp = sS + tid * 29;
    ull*   whb = g_wh + gtid;
    ull*   h2b = g_h2 + gtid;

    for (int i = tid; i < 1152; i += NTHR) sW2s[i] = *(const ull2*)&cW2[i*4];
    for (int i = tid; i < 288;  i += NTHR) sWp1[i] = *(const ull2*)&cWp1[i*4];
    __syncthreads();

    unsigned mrow[9];
    #pragma unroll
    for (int i = 0; i < 9; i++) mrow[i] = __ldg(&g_mrow[i]);
    float c1r[3], c2r[3];
    #pragma unroll
    for (int h = 0; h < 3; h++) { c1r[h] = __ldg(&g_c12[h]); c2r[h] = __ldg(&g_c12[3+h]); }

    for (int b = gtid; b < B; b += stride) {

        // ================= layer-1 (rank-1 collapse): s1[h][i] =================
        {
            float og[9];
            #pragma unroll
            for (int n = 0; n < 9; n++) og[n] = g_obs[b*9 + n];
            #pragma unroll 1
            for (int h = 0; h < 3; h++) {
                const float c1h = c1r[h], c2h = c2r[h];
                float gg[9];
                #pragma unroll
                for (int j = 0; j < 9; j++) gg[j] = c2h * og[j];
                #pragma unroll
                for (int i = 0; i < 9; i++) {
                    const unsigned m = mrow[i];
                    const float fi = c1h * og[i];
                    float e[9], mx = -3.0e38f;
                    #pragma unroll
                    for (int j = 0; j < 9; j++) {
                        float x = lrelu(fi + gg[j]);
                        if (!((m >> j) & 1u)) x = MASKV;
                        e[j] = x; mx = fmaxf(mx, x);
                    }
                    float den = 0.f, num = 0.f;
                    #pragma unroll
                    for (int j = 0; j < 9; j++) {
                        float p = __expf(e[j] - mx);
                        den += p; num += p * og[j];
                    }
                    sTp[h*9 + i] = __fdividef(num, den);
                }
            }
        }

        // ================= layer-2 per head =================
        #pragma unroll 1
        for (int H = 0; H < 3; H++) {
            const ull2* wHs = sW2s + H*384;
            float f1a[9], f2a[9];

            // ---- GEMM in 3-row passes (W2 from SMEM broadcast) ----
            #pragma unroll 1
            for (int g3 = 0; g3 < 9; g3 += 3) {
                ull acc[3][8];
                #pragma unroll
                for (int r = 0; r < 3; r++)
                    #pragma unroll
                    for (int p = 0; p < 8; p++) acc[r][p] = 0ull;

                #pragma unroll 1
                for (int kh = 0; kh < 3; kh++) {
                    const float sA = sTp[kh*9 + g3];
                    const float sB = sTp[kh*9 + g3 + 1];
                    const float sC = sTp[kh*9 + g3 + 2];
                    #pragma unroll 4
                    for (int d = 0; d < 32; d++) {
                        const int k = kh*32 + d;
                        const float w1 = cW1[k];
                        const ull eA = dup2(elu(sA * w1));
                        const ull eB = dup2(elu(sB * w1));
                        const ull eC = dup2(elu(sC * w1));
                        const ull2* wk = wHs + k*4;
                        const ull2 wa = wk[0];
                        const ull2 wb = wk[1];
                        const ull2 wc = wk[2];
                        const ull2 wd = wk[3];
                        ffma2(acc[0][0], eA, wa.x); ffma2(acc[0][1], eA, wa.y);
                        ffma2(acc[0][2], eA, wb.x); ffma2(acc[0][3], eA, wb.y);
                        ffma2(acc[0][4], eA, wc.x); ffma2(acc[0][5], eA, wc.y);
                        ffma2(acc[0][6], eA, wd.x); ffma2(acc[0][7], eA, wd.y);
                        ffma2(acc[1][0], eB, wa.x); ffma2(acc[1][1], eB, wa.y);
                        ffma2(acc[1][2], eB, wb.x); ffma2(acc[1][3], eB, wb.y);
                        ffma2(acc[1][4], eB, wc.x); ffma2(acc[1][5], eB, wc.y);
                        ffma2(acc[1][6], eB, wd.x); ffma2(acc[1][7], eB, wd.y);
                        ffma2(acc[2][0], eC, wa.x); ffma2(acc[2][1], eC, wa.y);
                        ffma2(acc[2][2], eC, wb.x); ffma2(acc[2][3], eC, wb.y);
                        ffma2(acc[2][4], eC, wc.x); ffma2(acc[2][5], eC, wc.y);
                        ffma2(acc[2][6], eC, wd.x); ffma2(acc[2][7], eC, wd.y);
                    }
                }
                #pragma unroll
                for (int r = 0; r < 3; r++) {
                    float f1 = 0.f, f2 = 0.f;
                    #pragma unroll
                    for (int p = 0; p < 8; p++) {
                        float2 t = unp(acc[r][p]);
                        f1 += t.x * cA2[H*32 + 2*p]      + t.y * cA2[H*32 + 2*p + 1];
                        f2 += t.x * cA2[H*32 + 16 + 2*p] + t.y * cA2[H*32 + 17 + 2*p];
                    }
                    f1a[g3 + r] = f1;
                    f2a[g3 + r] = f2;
                    #pragma unroll
                    for (int p = 0; p < 8; p++)
                        whb[((g3 + r)*8 + p)*NT] = acc[r][p];
                }
            }

            // ---- attention apply for head H ----
            #pragma unroll 1
            for (int i = 0; i < 9; i++) {
                const unsigned m = mrow[i];
                const float f1i = f1a[i];
                float e[9], mx = -3.0e38f;
                #pragma unroll
                for (int j = 0; j < 9; j++) {
                    float x = lrelu(f1i + f2a[j]);
                    if (!((m >> j) & 1u)) x = MASKV;
                    e[j] = x; mx = fmaxf(mx, x);
                }
                float den = 0.f;
                #pragma unroll
                for (int j = 0; j < 9; j++) { e[j] = __expf(e[j] - mx); den += e[j]; }
                const float inv = __fdividef(1.f, den);

                ull h2a[8];
                #pragma unroll
                for (int p = 0; p < 8; p++) h2a[p] = 0ull;
                #pragma unroll
                for (int j = 0; j < 9; j++) {
                    const ull wd = dup2(e[j] * inv);
                    #pragma unroll
                    for (int p = 0; p < 8; p++)
                        ffma2(h2a[p], whb[(j*8 + p)*NT], wd);
                }
                #pragma unroll
                for (int p = 0; p < 8; p++)
                    h2b[(i*24 + H*8 + p)*NT] = h2a[p];
            }
        }

        // ================= pooling (Wp1 from SMEM broadcast) =================
        float scl[9];
        #pragma unroll 1
        for (int n = 0; n < 9; n++) {
            ull U[12];
            #pragma unroll
            for (int mp = 0; mp < 12; mp++) U[mp] = c64(&cBp1[2*mp]);
            #pragma unroll 4
            for (int cp = 0; cp < 24; cp++) {
                float2 hv = unp(h2b[(n*24 + cp)*NT]);
                ull hx = dup2(hv.x), hy = dup2(hv.y);
                #pragma unroll
                for (int mq = 0; mq < 6; mq++) {
                    ull2 wa = sWp1[(2*cp    )*6 + mq];
                    ull2 wb = sWp1[(2*cp + 1)*6 + mq];
                    ffma2(U[2*mq],     hx, wa.x);
                    ffma2(U[2*mq + 1], hx, wa.y);
                    ffma2(U[2*mq],     hy, wb.x);
                    ffma2(U[2*mq + 1], hy, wb.y);
                }
            }
            float s = cBp2[0];
            #pragma unroll
            for (int mp = 0; mp < 12; mp++) {
                float2 u = unp(U[mp]);
                s += tanh_fast(u.x) * cWp2[2*mp] + tanh_fast(u.y) * cWp2[2*mp + 1];
            }
            scl[n] = s;
        }

        float mx = scl[0];
        #pragma unroll
        for (int n = 1; n < 9; n++) mx = fmaxf(mx, scl[n]);
        float den = 0.f, wnl[9];
        #pragma unroll
        for (int n = 0; n < 9; n++) { float p = __expf(scl[n] - mx); wnl[n] = p; den += p; }
        const float iv = __fdividef(1.f, den);

        ull outp[24];
        #pragma unroll
        for (int p = 0; p < 24; p++) outp[p] = 0ull;
        #pragma unroll 1
        for (int n = 0; n < 9; n++) {
            const ull wd = dup2(wnl[n] * iv);
            #pragma unroll
            for (int p = 0; p < 24; p++)
                ffma2(outp[p], h2b[(n*24 + p)*NT], wd);
        }
        #pragma unroll
        for (int p = 0; p < 24; p++)
            *(ull*)&g_out[(size_t)b*48 + 2*p] = outp[p];
    }
}

extern "C" void kernel_launch(void* const* d_in, const int* in_sizes, int n_in,
                              void* d_out, int out_size) {
    const float* obs = (const float*)d_in[0];
    int B = in_sizes[0] / 9;

    cudaMemcpyToSymbolAsync(cAdj, d_in[1],   81 * 4, 0, cudaMemcpyDeviceToDevice);
    cudaMemcpyToSymbolAsync(cW1,  d_in[2],   96 * 4, 0, cudaMemcpyDeviceToDevice);
    cudaMemcpyToSymbolAsync(cA1,  d_in[3],  192 * 4, 0, cudaMemcpyDeviceToDevice);
    cudaMemcpyToSymbolAsync(cW2,  d_in[4], 4608 * 4, 0, cudaMemcpyDeviceToDevice);
    cudaMemcpyToSymbolAsync(cA2,  d_in[5],   96 * 4, 0, cudaMemcpyDeviceToDevice);
    cudaMemcpyToSymbolAsync(cWp1, d_in[6], 1152 * 4, 0, cudaMemcpyDeviceToDevice);
    cudaMemcpyToSymbolAsync(cBp1, d_in[7],   24 * 4, 0, cudaMemcpyDeviceToDevice);
    cudaMemcpyToSymbolAsync(cWp2, d_in[8],   24 * 4, 0, cudaMemcpyDeviceToDevice);
    cudaMemcpyToSymbolAsync(cBp2, d_in[9],    1 * 4, 0, cudaMemcpyDeviceToDevice);

    int blocks = (B + NTHR - 1) / NTHR;
    if (blocks > MAXBLK) blocks = MAXBLK;

    prep_kernel<<<1, 32>>>();
    gnn_main<<<blocks, NTHR>>>(obs, (float*)d_out, B);
}